// round 9
// baseline (speedup 1.0000x reference)
#include <cuda_runtime.h>
#include <cuda_fp16.h>
#include <cstdint>

// Correlation layer via band-restricted mma.sync (m16n8k16 fp16, fp32 accum).
// out[b, di*9+dj, h, w] = sum_c f1[b,c,h,w] * f2[b,c,h+di-4,w+dj-4]
// B=8, C=256, H=64, W=128, D=81.
//
// R9: f2 pre-cast into a PADDED fp16 gmem layout [b][c][h][136] (zero halos in
//     gmem) -> all-16B cp.async, no smem zeroing. CTA split into two
//     independent half-CTAs (warps 0-7: di 0-3, warps 8-15: di 4-8) with
//     private buffers + named barriers -> the halves overlap each other's
//     pipeline stalls. B-tiles via ldsm4t pair + ldsm2t (2 MIO ops per r).

#define NB 8
#define NC 256
#define NH 64
#define NW 128
#define ND 81
#define PW 136                       // padded f2 row (halves); data at [4,132)

#define RSTRIDE 272                  // bytes per f2 c-row in smem (=PW*2); %128==16 -> LDSM conflict-free
#define F2ROW (16 * RSTRIDE)         // 4352 B per (r) per 16-c chunk
#define F1STR 132                    // f1 fp32 smem row stride in words (528 B)
#define F1SZ (16 * F1STR * 4)        // 8448 B
#define NBUF 3
#define BUF0 (4 * F2ROW + F1SZ)      // half0 buffer: 25856 B
#define BUF1 (5 * F2ROW + F1SZ)      // half1 buffer: 30208 B
#define HALF1_BASE (NBUF * BUF0)     // 77568
#define SMEM_SZ (HALF1_BASE + NBUF * BUF1)   // 168192 B
#define STAGE_W 25

__device__ __half g_f2h[(size_t)NB * NC * NH * PW];

// ---------------- fp32 -> padded fp16 cast for f2 ----------------
__global__ void cast_kernel(const float* __restrict__ f2) {
    int idx = blockIdx.x * 256 + threadIdx.x;   // one 16B output seg
    int row = idx / 17, sg = idx % 17;          // row = ((b*NC+c)*NH+h)
    const float* src = f2 + (size_t)row * NW;
    __half hv[8];
    #pragma unroll
    for (int k = 0; k < 8; k++) {
        int col = 8 * sg - 4 + k;
        float v = (col >= 0 && col < NW) ? src[col] : 0.0f;
        hv[k] = __float2half_rn(v);
    }
    *reinterpret_cast<uint4*>(g_f2h + (size_t)row * PW + 8 * sg) =
        *reinterpret_cast<const uint4*>(hv);
}

// ---------------- PTX helpers ----------------
__device__ __forceinline__ void cpa16(uint32_t dst, const void* src) {
    asm volatile("cp.async.ca.shared.global [%0], [%1], 16;" :: "r"(dst), "l"(src));
}
__device__ __forceinline__ void ldsm4t(uint32_t& r0, uint32_t& r1,
                                       uint32_t& r2, uint32_t& r3, uint32_t a) {
    asm volatile("ldmatrix.sync.aligned.m8n8.x4.trans.shared.b16 {%0,%1,%2,%3}, [%4];"
                 : "=r"(r0), "=r"(r1), "=r"(r2), "=r"(r3) : "r"(a));
}
__device__ __forceinline__ void ldsm2t(uint32_t& r0, uint32_t& r1, uint32_t a) {
    asm volatile("ldmatrix.sync.aligned.m8n8.x2.trans.shared.b16 {%0,%1}, [%2];"
                 : "=r"(r0), "=r"(r1) : "r"(a));
}
__device__ __forceinline__ void mma16816(float* d, uint32_t a0, uint32_t a1,
                                         uint32_t a2, uint32_t a3,
                                         uint32_t b0, uint32_t b1) {
    asm volatile("mma.sync.aligned.m16n8k16.row.col.f32.f16.f16.f32 "
                 "{%0,%1,%2,%3}, {%4,%5,%6,%7}, {%8,%9}, {%0,%1,%2,%3};"
                 : "+f"(d[0]), "+f"(d[1]), "+f"(d[2]), "+f"(d[3])
                 : "r"(a0), "r"(a1), "r"(a2), "r"(a3), "r"(b0), "r"(b1));
}
__device__ __forceinline__ uint32_t pkh2(float lo, float hi) {
    __half2 h = __floats2half2_rn(lo, hi);
    return *reinterpret_cast<uint32_t*>(&h);
}
#define HBAR(id) asm volatile("bar.sync %0, 256;" :: "r"(id) : "memory")

// ---------------- main kernel ----------------
__global__ void __launch_bounds__(512, 1)
corr_mma(const float* __restrict__ f1, float* __restrict__ out) {
    extern __shared__ char smem[];
    const uint32_t sb = (uint32_t)__cvta_generic_to_shared(smem);
    const int tid = threadIdx.x;
    const int lane = tid & 31, warp = tid >> 5;
    const int m = warp & 7, half = warp >> 3;   // m16 w-block; r-half
    const int tid256 = tid & 255;
    const int h = blockIdx.x, b = blockIdx.y;
    const size_t bbase = (size_t)b * NC * NH * NW;

    const int R0 = half ? 4 : 0;
    const int RN = half ? 5 : 4;
    const int BUFSZ = half ? BUF1 : BUF0;
    const uint32_t hbase = sb + (half ? HALF1_BASE : 0);
    const int OFFF1 = RN * F2ROW;
    const int NTASK = RN * 272;      // f2 16B segs per chunk per half

    float acc[5][3][4];
    #pragma unroll
    for (int ri = 0; ri < 5; ri++)
        #pragma unroll
        for (int t = 0; t < 3; t++)
            #pragma unroll
            for (int k = 0; k < 4; k++)
                acc[ri][t][k] = 0.0f;

    // A fragment source (f1 fp32 in smem, [k][w] stride F1STR words).
    const int gid = lane >> 2, tig = lane & 3;
    const uint32_t a_word0 = (uint32_t)(2 * tig) * F1STR + 16 * m + gid;
    // B ldsm addresses: x4 -> tiles (16m, 16m+8); x2 -> tile 16m+16.
    const uint32_t b4_off = (uint32_t)(lane & 15) * RSTRIDE + ((lane >> 4) << 4) + 32 * m;
    const uint32_t b2_off = (uint32_t)(lane & 15) * RSTRIDE + 32 * m + 32;

    auto issue = [&](int cc) {
        const int c0 = cc * 16;
        const uint32_t dbase = hbase + (cc % NBUF) * BUFSZ;
        #pragma unroll
        for (int s = 0; s < 6; s++) {
            int t = tid256 + 256 * s;
            if (t < NTASK) {
                int r = t / 272, rem = t % 272;
                int ci = rem / 17, sg = rem % 17;
                int gr = h + R0 + r - 4;
                gr = gr < 0 ? 0 : (gr > NH - 1 ? NH - 1 : gr);  // clamp; invalid di never stored
                const __half* src = g_f2h + ((size_t)(b * NC + c0 + ci) * NH + gr) * PW + 8 * sg;
                cpa16(dbase + r * F2ROW + ci * RSTRIDE + 16 * sg, src);
            }
        }
        #pragma unroll
        for (int s = 0; s < 2; s++) {
            int t = tid256 + 256 * s;
            int ci = t >> 5, sg = t & 31;
            const float* src = f1 + bbase + ((size_t)(c0 + ci) * NH + h) * NW + 4 * sg;
            cpa16(dbase + OFFF1 + ci * (F1STR * 4) + 16 * sg, src);
        }
    };

    issue(0);
    asm volatile("cp.async.commit_group;");
    issue(1);
    asm volatile("cp.async.commit_group;");

    for (int cc = 0; cc < 16; cc++) {
        asm volatile("cp.async.wait_group 1;");   // chunk cc complete
        HBAR(1 + half);
        if (cc + 2 < 16) issue(cc + 2);           // buf (cc+2)%3 == (cc-1)%3: consumed, all passed bar
        asm volatile("cp.async.commit_group;");   // empty at tail keeps count uniform

        const uint32_t cbase = hbase + (cc % NBUF) * BUFSZ;
        const float* fp = reinterpret_cast<const float*>(
            smem + (half ? HALF1_BASE : 0) + (cc % NBUF) * BUFSZ + OFFF1) + a_word0;
        uint32_t a0 = pkh2(fp[0],             fp[F1STR]);
        uint32_t a1 = pkh2(fp[8],             fp[F1STR + 8]);
        uint32_t a2 = pkh2(fp[8 * F1STR],     fp[9 * F1STR]);
        uint32_t a3 = pkh2(fp[8 * F1STR + 8], fp[9 * F1STR + 8]);

        #pragma unroll
        for (int ri = 0; ri < 5; ri++) {
            if (ri < RN) {
                const uint32_t rb = cbase + ri * F2ROW;
                uint32_t q0, q1, q2, q3, e0, e1;
                ldsm4t(q0, q1, q2, q3, rb + b4_off);
                ldsm2t(e0, e1, rb + b2_off);
                mma16816(acc[ri][0], a0, a1, a2, a3, q0, q1);
                mma16816(acc[ri][1], a0, a1, a2, a3, q2, q3);
                mma16816(acc[ri][2], a0, a1, a2, a3, e0, e1);
            }
        }
    }

    // ---------------- epilogue: band extraction via per-warp staging ----------------
    HBAR(1 + half);   // all half-warps done with buffers before aliasing them
    float* stage = reinterpret_cast<float*>(smem + (half ? HALF1_BASE : 0))
                 + (warp & 7) * 16 * STAGE_W;
    const int l16 = lane & 15, dh = lane >> 4;
    #pragma unroll
    for (int ri = 0; ri < 5; ri++) {
        if (ri < RN) {
            const int r = R0 + ri;
            #pragma unroll
            for (int t = 0; t < 3; t++) {
                stage[gid * STAGE_W + 8 * t + 2 * tig]           = acc[ri][t][0];
                stage[gid * STAGE_W + 8 * t + 2 * tig + 1]       = acc[ri][t][1];
                stage[(gid + 8) * STAGE_W + 8 * t + 2 * tig]     = acc[ri][t][2];
                stage[(gid + 8) * STAGE_W + 8 * t + 2 * tig + 1] = acc[ri][t][3];
            }
            __syncwarp();
            const int gr = h + r - 4;
            const bool valid = (gr >= 0 && gr < NH);
            // out[b, r*9+dj, h, 16m+l16] = band[l16][l16+dj] (padded-col space)
            #pragma unroll
            for (int rd = 0; rd < 5; rd++) {
                int dj = 2 * rd + dh;
                if (dj < 9) {
                    float v = valid ? stage[l16 * STAGE_W + l16 + dj] : 0.0f;
                    out[(((size_t)b * ND + r * 9 + dj) * NH + h) * NW + 16 * m + l16] = v;
                }
            }
            __syncwarp();
        }
    }
}

extern "C" void kernel_launch(void* const* d_in, const int* in_sizes, int n_in,
                              void* d_out, int out_size) {
    const float* f1 = (const float*)d_in[0];
    const float* f2 = (const float*)d_in[1];
    float* out = (float*)d_out;

    cudaFuncSetAttribute(corr_mma, cudaFuncAttributeMaxDynamicSharedMemorySize, SMEM_SZ);

    // (NB*NC*NH rows) * 17 segs / 256 threads = 8704 blocks exactly
    cast_kernel<<<8704, 256>>>(f2);
    corr_mma<<<dim3(NH, NB), 512, SMEM_SZ>>>(f1, out);
}

// round 10
// speedup vs baseline: 1.0004x; 1.0004x over previous
#include <cuda_runtime.h>
#include <cuda_fp16.h>
#include <cstdint>

// Correlation layer via band-restricted mma.sync (m16n8k16 fp16, fp32 accum).
// out[b, di*9+dj, h, w] = sum_c f1[b,c,h,w] * f2[b,c,h+di-4,w+dj-4]
// B=8, C=256, H=64, W=128, D=81.
//
// R10: CTA per (h, b, half): half 0 -> di 0-3, half 1 -> di 4-8; 256 threads,
//      8 warps = 8 m16 w-blocks, acc <= 60 regs -> 2 CTAs/SM co-resident
//      (independent pipelines hide each other's stalls). f2 pre-cast to a
//      padded fp16 gmem layout [b][c][h][136] (zero halos) -> all-16B
//      division-free cp.async. f1 consumed fp32 directly.

#define NB 8
#define NC 256
#define NH 64
#define NW 128
#define ND 81
#define PW 136                       // padded f2 row (halves); data at cols [4,132)

#define RSTRIDE 272                  // f2 c-row bytes in smem (=PW*2); %128==16 -> LDSM conflict-free
#define F2ROW (16 * RSTRIDE)         // 4352 B per r per 16-c chunk
#define F1STR 132                    // f1 fp32 smem row stride in words (528 B)
#define F1SZ (16 * F1STR * 4)        // 8448 B
#define OFFF1 (5 * F2ROW)            // 21760 (worst-case RN=5 layout for both halves)
#define BUFSZ (OFFF1 + F1SZ)         // 30208
#define NBUF 3
#define SMEM_SZ (NBUF * BUFSZ)       // 90624 B -> 2 CTAs/SM
#define STAGE_W 25

__device__ __half g_f2h[(size_t)NB * NC * NH * PW];

// ---------------- fp32 -> padded fp16 cast for f2 ----------------
__global__ void cast_kernel(const float* __restrict__ f2) {
    int idx = blockIdx.x * 256 + threadIdx.x;   // one 16B output seg
    int row = idx / 17, sg = idx % 17;          // row = ((b*NC+c)*NH+h)
    const float* src = f2 + (size_t)row * NW;
    __half hv[8];
    #pragma unroll
    for (int k = 0; k < 8; k++) {
        int col = 8 * sg - 4 + k;
        float v = (col >= 0 && col < NW) ? src[col] : 0.0f;
        hv[k] = __float2half_rn(v);
    }
    *reinterpret_cast<uint4*>(g_f2h + (size_t)row * PW + 8 * sg) =
        *reinterpret_cast<const uint4*>(hv);
}

// ---------------- PTX helpers ----------------
__device__ __forceinline__ void cpa16(uint32_t dst, const void* src) {
    asm volatile("cp.async.ca.shared.global [%0], [%1], 16;" :: "r"(dst), "l"(src));
}
__device__ __forceinline__ void ldsm4t(uint32_t& r0, uint32_t& r1,
                                       uint32_t& r2, uint32_t& r3, uint32_t a) {
    asm volatile("ldmatrix.sync.aligned.m8n8.x4.trans.shared.b16 {%0,%1,%2,%3}, [%4];"
                 : "=r"(r0), "=r"(r1), "=r"(r2), "=r"(r3) : "r"(a));
}
__device__ __forceinline__ void ldsm2t(uint32_t& r0, uint32_t& r1, uint32_t a) {
    asm volatile("ldmatrix.sync.aligned.m8n8.x2.trans.shared.b16 {%0,%1}, [%2];"
                 : "=r"(r0), "=r"(r1) : "r"(a));
}
__device__ __forceinline__ void mma16816(float* d, uint32_t a0, uint32_t a1,
                                         uint32_t a2, uint32_t a3,
                                         uint32_t b0, uint32_t b1) {
    asm volatile("mma.sync.aligned.m16n8k16.row.col.f32.f16.f16.f32 "
                 "{%0,%1,%2,%3}, {%4,%5,%6,%7}, {%8,%9}, {%0,%1,%2,%3};"
                 : "+f"(d[0]), "+f"(d[1]), "+f"(d[2]), "+f"(d[3])
                 : "r"(a0), "r"(a1), "r"(a2), "r"(a3), "r"(b0), "r"(b1));
}
__device__ __forceinline__ uint32_t pkh2(float lo, float hi) {
    __half2 h = __floats2half2_rn(lo, hi);
    return *reinterpret_cast<uint32_t*>(&h);
}

// ---------------- main kernel ----------------
__global__ void __launch_bounds__(256, 2)
corr_mma(const float* __restrict__ f1, float* __restrict__ out) {
    extern __shared__ char smem[];
    const uint32_t sb = (uint32_t)__cvta_generic_to_shared(smem);
    const int tid = threadIdx.x;
    const int lane = tid & 31, m = tid >> 5;    // warp = m16 w-block
    const int h = blockIdx.x, b = blockIdx.y, half = blockIdx.z;
    const size_t bbase = (size_t)b * NC * NH * NW;

    const int R0 = half ? 4 : 0;
    const int RN = half ? 5 : 4;

    float acc[5][3][4];
    #pragma unroll
    for (int ri = 0; ri < 5; ri++)
        #pragma unroll
        for (int t = 0; t < 3; t++)
            #pragma unroll
            for (int k = 0; k < 4; k++)
                acc[ri][t][k] = 0.0f;

    // A fragments from fp32 f1 in smem ([k][w], stride F1STR words).
    const int gid = lane >> 2, tig = lane & 3;
    const uint32_t a_word0 = (uint32_t)(2 * tig) * F1STR + 16 * m + gid;
    // B ldsm addresses: x4 -> tiles at padded cols (16m, 16m+8); x2 -> 16m+16.
    const uint32_t b4_off = (uint32_t)(lane & 15) * RSTRIDE + ((lane >> 4) << 4) + 32 * m;
    const uint32_t b2_off = (uint32_t)(lane & 15) * RSTRIDE + 32 * m + 32;

    // Division-free loader: thread (ci, sg) = (tid>>4, tid&15) copies seg sg of
    // each r's row; sg==0 threads also copy the 17th seg. f1: 2 segs/thread.
    const int ci = tid >> 4, sg = tid & 15;
    auto issue = [&](int cc) {
        const int c0 = cc * 16;
        const uint32_t dbase = sb + (cc % NBUF) * BUFSZ;
        #pragma unroll
        for (int r = 0; r < 5; r++) {
            if (r < RN) {
                int gr = h + R0 + r - 4;
                gr = gr < 0 ? 0 : (gr > NH - 1 ? NH - 1 : gr);  // clamp; invalid di never stored
                const __half* rowp = g_f2h + ((size_t)(b * NC + c0 + ci) * NH + gr) * PW;
                const uint32_t d = dbase + r * F2ROW + ci * RSTRIDE;
                cpa16(d + 16 * sg, rowp + 8 * sg);
                if (sg == 0) cpa16(d + 256, rowp + 128);
            }
        }
        #pragma unroll
        for (int s = 0; s < 2; s++) {
            int t = tid + 256 * s;
            int c2 = t >> 5, s2 = t & 31;
            const float* src = f1 + bbase + ((size_t)(c0 + c2) * NH + h) * NW + 4 * s2;
            cpa16(dbase + OFFF1 + c2 * (F1STR * 4) + 16 * s2, src);
        }
    };

    issue(0);
    asm volatile("cp.async.commit_group;");
    issue(1);
    asm volatile("cp.async.commit_group;");

    for (int cc = 0; cc < 16; cc++) {
        asm volatile("cp.async.wait_group 1;");   // chunk cc complete
        __syncthreads();
        if (cc + 2 < 16) issue(cc + 2);           // buf (cc+2)%3 == (cc-1)%3: consumed before barrier
        asm volatile("cp.async.commit_group;");   // empty at tail keeps count uniform

        const uint32_t cbase = sb + (cc % NBUF) * BUFSZ;
        const float* fp = reinterpret_cast<const float*>(
            smem + (cc % NBUF) * BUFSZ + OFFF1) + a_word0;
        uint32_t a0 = pkh2(fp[0],             fp[F1STR]);
        uint32_t a1 = pkh2(fp[8],             fp[F1STR + 8]);
        uint32_t a2 = pkh2(fp[8 * F1STR],     fp[9 * F1STR]);
        uint32_t a3 = pkh2(fp[8 * F1STR + 8], fp[9 * F1STR + 8]);

        #pragma unroll
        for (int ri = 0; ri < 5; ri++) {
            if (ri < RN) {
                const uint32_t rb = cbase + ri * F2ROW;
                uint32_t q0, q1, q2, q3, e0, e1;
                ldsm4t(q0, q1, q2, q3, rb + b4_off);
                ldsm2t(e0, e1, rb + b2_off);
                mma16816(acc[ri][0], a0, a1, a2, a3, q0, q1);
                mma16816(acc[ri][1], a0, a1, a2, a3, q2, q3);
                mma16816(acc[ri][2], a0, a1, a2, a3, e0, e1);
            }
        }
    }

    // ---------------- epilogue: band extraction via per-warp staging ----------------
    __syncthreads();   // buffers dead; staging aliases them
    float* stage = reinterpret_cast<float*>(smem) + m * 16 * STAGE_W;
    const int l16 = lane & 15, dh = lane >> 4;
    #pragma unroll
    for (int ri = 0; ri < 5; ri++) {
        if (ri < RN) {
            const int r = R0 + ri;
            #pragma unroll
            for (int t = 0; t < 3; t++) {
                stage[gid * STAGE_W + 8 * t + 2 * tig]           = acc[ri][t][0];
                stage[gid * STAGE_W + 8 * t + 2 * tig + 1]       = acc[ri][t][1];
                stage[(gid + 8) * STAGE_W + 8 * t + 2 * tig]     = acc[ri][t][2];
                stage[(gid + 8) * STAGE_W + 8 * t + 2 * tig + 1] = acc[ri][t][3];
            }
            __syncwarp();
            const int gr = h + r - 4;
            const bool valid = (gr >= 0 && gr < NH);
            // out[b, r*9+dj, h, 16m+l16] = band[l16][l16+dj] (padded-col space)
            #pragma unroll
            for (int rd = 0; rd < 5; rd++) {
                int dj = 2 * rd + dh;
                if (dj < 9) {
                    float v = valid ? stage[l16 * STAGE_W + l16 + dj] : 0.0f;
                    out[(((size_t)b * ND + r * 9 + dj) * NH + h) * NW + 16 * m + l16] = v;
                }
            }
            __syncwarp();
        }
    }
}

extern "C" void kernel_launch(void* const* d_in, const int* in_sizes, int n_in,
                              void* d_out, int out_size) {
    const float* f1 = (const float*)d_in[0];
    const float* f2 = (const float*)d_in[1];
    float* out = (float*)d_out;

    cudaFuncSetAttribute(corr_mma, cudaFuncAttributeMaxDynamicSharedMemorySize, SMEM_SZ);

    // (NB*NC*NH rows) * 17 segs / 256 threads = 8704 blocks exactly
    cast_kernel<<<8704, 256>>>(f2);
    corr_mma<<<dim3(NH, NB, 2), 256, SMEM_SZ>>>(f1, out);
}